// round 15
// baseline (speedup 1.0000x reference)
#include <cuda_runtime.h>
#include <cuda_bf16.h>
#include <cstdint>

#define BATCH 65536
#define D 128
#define OUTW 896
#define ROWS 64                       // batch rows per block (MMA M total)
#define THREADS 256
#define NBLOCKS (BATCH / ROWS)        // 1024
#define SLOTS_PER_ROW 384
#define BAS_ITERS (ROWS * SLOTS_PER_ROW / THREADS)   // 96

// K-chunked smem: chunk = 64 K-cols, stride 72 elems (144B = 9x16B, ldmatrix conflict-free)
#define TS 72
#define SM_AH 0                       // x2_hi  [64][72] bf16 = 9216 B
#define SM_AL 9216                    // x2_lo
#define SM_BH 18432                   // S^T_hi [128][72] bf16 = 18432 B
#define SM_BL 36864                   // S^T_lo
#define SM_TOTAL 55296                // -> 4 CTAs/SM

__device__ __align__(16) uint16_t g_SB[2 * 128 * 128];  // [hi | lo] S^T, unpadded [c][i]

// ---------------- helpers ----------------
__device__ __forceinline__ uint32_t smem_u32(const void* p) {
    uint32_t a;
    asm("{ .reg .u64 t; cvta.to.shared.u64 t, %1; cvt.u32.u64 %0, t; }" : "=r"(a) : "l"(p));
    return a;
}
#define LDMX4(r0, r1, r2, r3, addr)                                        \
    asm volatile("ldmatrix.sync.aligned.m8n8.x4.shared.b16 {%0,%1,%2,%3}, [%4];" \
                 : "=r"(r0), "=r"(r1), "=r"(r2), "=r"(r3) : "r"(addr))
#define MMA16816(d, a0, a1, a2, a3, b0, b1)                                \
    asm volatile("mma.sync.aligned.m16n8k16.row.col.f32.bf16.bf16.f32 "    \
                 "{%0,%1,%2,%3}, {%4,%5,%6,%7}, {%8,%9}, {%0,%1,%2,%3};"   \
                 : "+f"((d)[0]), "+f"((d)[1]), "+f"((d)[2]), "+f"((d)[3])  \
                 : "r"(a0), "r"(a1), "r"(a2), "r"(a3), "r"(b0), "r"(b1))

// cardinal cubic B-spline: support (0,4), symmetric about y=2
__device__ __forceinline__ float bspl(float y) {
    float z = fminf(y, 4.0f - y);
    z = fmaxf(z, 0.0f);
    float lo = z * z * z * (1.0f / 6.0f);
    float t = 2.0f - z;
    float hi = fmaf(t * t, fmaf(t, 0.5f, -1.0f), 2.0f / 3.0f);
    return (z < 1.0f) ? lo : hi;
}
__device__ __forceinline__ void split_bf16(float v, uint16_t& h, uint16_t& l) {
    __nv_bfloat16 hb = __float2bfloat16(v);
    __nv_bfloat16 lb = __float2bfloat16(v - __bfloat162float(hb));
    h = __bfloat16_as_ushort(hb);
    l = __bfloat16_as_ushort(lb);
}

// ---------------- kernel 1: build S^T hi/lo images ----------------
__global__ void prep_kernel(const float* __restrict__ W) {
    int idx = blockIdx.x * blockDim.x + threadIdx.x;   // 16384
    if (idx < D * D) {
        int c = idx & 127;
        int i = idx >> 7;
        float s = 1.0f / (1.0f + expf(-W[i * D + c]));
        uint16_t h, l;
        split_bf16(s, h, l);
        g_SB[c * D + i] = h;
        g_SB[D * D + c * D + i] = l;
    }
}

// ---------------- kernel 2: fused HMMA interaction + basis ----------------
__global__ __launch_bounds__(THREADS, 4) void kan_kernel(const float* __restrict__ x,
                                                         float* __restrict__ out) {
    extern __shared__ __align__(16) char smem[];
    const int tid = threadIdx.x;
    const int wid = tid >> 5;
    const int lid = tid & 31;
    const int r0 = blockIdx.x * ROWS;

    const uint32_t sb = smem_u32(smem);
    const int m0 = (wid & 3) * 16;
    const int c0 = (wid >> 2) * 64;
    const int t = lid >> 3;
    const int tr = lid & 7;

    // ldmatrix lane offsets (within a chunk tile, stride TS)
    const uint32_t aoff =
        (uint32_t)((m0 + (t & 1) * 8 + tr) * (TS * 2) + (t >> 1) * 16);
    uint32_t boff[4];
#pragma unroll
    for (int p = 0; p < 4; p++)
        boff[p] = (uint32_t)((c0 + p * 16 + (t >> 1) * 8 + tr) * (TS * 2) +
                             (t & 1) * 16);

    float acc[8][4];
#pragma unroll
    for (int n = 0; n < 8; n++)
#pragma unroll
        for (int j = 0; j < 4; j++) acc[n][j] = 0.0f;

    // ---- GEMM over 2 K-chunks of 64 ----
#pragma unroll 1
    for (int ch = 0; ch < 2; ch++) {
        __syncthreads();   // previous chunk fully consumed (no-op cost on ch=0)

        // stage A: x^2 hi/lo. thread -> (row r, float4-quad q4) of this chunk
        {
            uint16_t* sah = (uint16_t*)(smem + SM_AH);
            uint16_t* sal = (uint16_t*)(smem + SM_AL);
#pragma unroll
            for (int j = 0; j < 4; j++) {
                int idx = tid + j * 256;        // 0..1023
                int r = idx >> 4;
                int q4 = idx & 15;
                float4 f = *(const float4*)(x + (size_t)(r0 + r) * D + ch * 64 + q4 * 4);
                float q0 = f.x * f.x, q1 = f.y * f.y, q2 = f.z * f.z, q3 = f.w * f.w;
                uint16_t h0, l0, h1, l1, h2, l2, h3, l3;
                split_bf16(q0, h0, l0);
                split_bf16(q1, h1, l1);
                split_bf16(q2, h2, l2);
                split_bf16(q3, h3, l3);
                int d0 = r * TS + q4 * 4;
                *(uint2*)(sah + d0) = make_uint2((uint32_t)h0 | ((uint32_t)h1 << 16),
                                                 (uint32_t)h2 | ((uint32_t)h3 << 16));
                *(uint2*)(sal + d0) = make_uint2((uint32_t)l0 | ((uint32_t)l1 << 16),
                                                 (uint32_t)l2 | ((uint32_t)l3 << 16));
            }
        }
        // stage B: S^T hi/lo chunk copy. thread -> (c, 8-elem group)
        {
            const uint4* gh = (const uint4*)(g_SB);
            const uint4* gl = (const uint4*)(g_SB + D * D);
            uint16_t* sbh = (uint16_t*)(smem + SM_BH);
            uint16_t* sbl = (uint16_t*)(smem + SM_BL);
#pragma unroll
            for (int j = 0; j < 4; j++) {
                int idx = tid + j * 256;        // 0..1023
                int c = idx >> 3;
                int g8 = idx & 7;
                // source uint4 index: (c*128 + ch*64 + g8*8) / 8
                int src = c * 16 + ch * 8 + g8;
                int d0 = c * TS + g8 * 8;
                *(uint4*)(sbh + d0) = gh[src];
                *(uint4*)(sbl + d0) = gl[src];
            }
        }
        __syncthreads();

        // compute: 3 passes (AhBh, AlBh, AhBl) x 4 k-steps of 16
        const uint32_t abase[3] = {sb + SM_AH, sb + SM_AL, sb + SM_AH};
        const uint32_t bbase[3] = {sb + SM_BH, sb + SM_BH, sb + SM_BL};
#pragma unroll
        for (int pass = 0; pass < 3; pass++) {
            uint32_t ab = abase[pass] + aoff;
            uint32_t bbs = bbase[pass];
#pragma unroll
            for (int k = 0; k < 4; k++) {
                uint32_t kb = (uint32_t)k * 32;
                uint32_t a0, a1, a2, a3;
                LDMX4(a0, a1, a2, a3, ab + kb);
#pragma unroll
                for (int p = 0; p < 4; p++) {
                    uint32_t b0, b1, b2, b3;
                    LDMX4(b0, b1, b2, b3, bbs + boff[p] + kb);
                    MMA16816(acc[2 * p], a0, a1, a2, a3, b0, b1);
                    MMA16816(acc[2 * p + 1], a0, a1, a2, a3, b2, b3);
                }
            }
        }
    }

    // ---- GEMM epilogue ----
    {
        const int row_a = r0 + m0 + (lid >> 2);
        const int colb = 768 + c0 + (lid & 3) * 2;
#pragma unroll
        for (int nt = 0; nt < 8; nt++) {
            *(float2*)&out[(size_t)row_a * OUTW + colb + nt * 8] =
                make_float2(acc[nt][0], acc[nt][1]);
            *(float2*)&out[(size_t)(row_a + 8) * OUTW + colb + nt * 8] =
                make_float2(acc[nt][2], acc[nt][3]);
        }
    }

    // ---- basis: dense float2 stores, cardinal closed form ----
    {
        const float* xb = x + (size_t)r0 * D;
#pragma unroll 4
        for (int s = 0; s < BAS_ITERS; s++) {
            int q = tid + s * THREADS;          // 0..24575
            int row = q / SLOTS_PER_ROW;
            int p = q - row * SLOTS_PER_ROW;
            int i = p / 3;
            int pr = p - i * 3;

            float xv = __ldg(&xb[row * D + i]);
            float px = fminf(fmaxf(fmaf(xv, 4.5f, 4.5f), 0.0f), 8.9999955f);
            float y0 = px - (float)(2 * pr);
            float v0 = bspl(y0);
            float v1 = bspl(y0 - 1.0f);

            float2* op = (float2*)(out + (size_t)(r0 + row) * OUTW) + p;
            *op = make_float2(v0, v1);
        }
    }
}

extern "C" void kernel_launch(void* const* d_in, const int* in_sizes, int n_in,
                              void* d_out, int out_size) {
    const float* x;
    const float* W;
    if (n_in >= 2 && in_sizes[0] == D * D && in_sizes[1] != D * D) {
        W = (const float*)d_in[0];
        x = (const float*)d_in[1];
    } else {
        x = (const float*)d_in[0];
        W = (const float*)d_in[1];
    }
    float* out = (float*)d_out;

    cudaFuncSetAttribute(kan_kernel, cudaFuncAttributeMaxDynamicSharedMemorySize, SM_TOTAL);

    prep_kernel<<<(D * D + 255) / 256, 256>>>(W);
    kan_kernel<<<NBLOCKS, THREADS, SM_TOTAL>>>(x, out);
}